// round 15
// baseline (speedup 1.0000x reference)
#include <cuda_runtime.h>
#include <cuda_bf16.h>
#include <math.h>

#define NQ 512
#define DM 1024
#define NEL (NQ * DM)

// ---------------- scratch ----------------
__device__ float    g_txt[NEL];           // f32 (residual)
__device__ float    g_img[NEL];
__device__ unsigned g_txt_tf[NEL];        // tf32 copies (GEMM A inputs)
__device__ unsigned g_img_tf[NEL];
__device__ float    g_Q[2][NEL];
__device__ float    g_K[2][NEL];
__device__ float    g_V[2][NEL];
__device__ unsigned g_O_tf[2][NEL];       // attention out, tf32
__device__ unsigned g_w_tf[10][DM * DM];
__device__ unsigned g_cap_tf[NQ * 768];
__device__ unsigned g_im_tf[NEL];

__device__ __forceinline__ unsigned f2tf32(float x) {
    unsigned u;
    asm("cvt.rna.tf32.f32 %0, %1;" : "=r"(u) : "f"(x));
    return u;
}
__device__ __forceinline__ uint4 cvt4(float4 v) {
    return make_uint4(f2tf32(v.x), f2tf32(v.y), f2tf32(v.z), f2tf32(v.w));
}

// ---------------- bulk f32 -> tf32 conversion ----------------
struct ConvArgs {
    const float* src[12];
    unsigned*    dst[12];
    int          n4[12];
};

__global__ __launch_bounds__(256) void conv_tf32_kernel(ConvArgs a) {
    const int z = blockIdx.y;
    const float4* __restrict__ s = (const float4*)a.src[z];
    uint4* __restrict__ d = (uint4*)a.dst[z];
    const int n4 = a.n4[z];
    for (int i = blockIdx.x * blockDim.x + threadIdx.x; i < n4; i += gridDim.x * blockDim.x)
        d[i] = cvt4(s[i]);
}

// ---------------------------------------------------------------------------
// tf32 GEMM (pre-converted inputs): C = A(512xK) @ W(1024xK)^T + bias (+resid)
// BM=128, BN=128, BK=32, 256 threads (8 warps, 4Mx2N, warp tile 32x64).
// cp.async 3-stage pipeline; fragment loads via ldmatrix.x4.
// ---------------------------------------------------------------------------
struct GemmArgs {
    const unsigned* A[6];
    const unsigned* W[6];
    const float*    bias[6];
    const float*    resid[6];
    float*          C[6];
    unsigned*       Ctf[6];
    int             K[6];
};

#define NSTAGE 3
#define A_TW (128 * 36)
#define W_TW (128 * 36)
#define GEMM_SMEM ((A_TW + W_TW) * NSTAGE * 4)   // 110592 B

__device__ __forceinline__ void cp_async16(unsigned smem_addr, const void* gptr) {
    asm volatile("cp.async.cg.shared.global [%0], [%1], 16;" :: "r"(smem_addr), "l"(gptr));
}
__device__ __forceinline__ void cp_commit() { asm volatile("cp.async.commit_group;"); }
__device__ __forceinline__ void cp_wait1()  { asm volatile("cp.async.wait_group 1;"); }

__device__ __forceinline__ void ldsm_x4(unsigned& r0, unsigned& r1, unsigned& r2, unsigned& r3,
                                        unsigned addr) {
    asm volatile("ldmatrix.sync.aligned.m8n8.x4.shared.b16 {%0,%1,%2,%3}, [%4];"
                 : "=r"(r0), "=r"(r1), "=r"(r2), "=r"(r3) : "r"(addr));
}

extern __shared__ unsigned smem_dyn[];

__global__ __launch_bounds__(256) void gemm_tf32_kernel(GemmArgs args) {
    const int z = blockIdx.z;
    const unsigned* __restrict__ A = args.A[z];
    const unsigned* __restrict__ W = args.W[z];
    const float* __restrict__ bias = args.bias[z];
    const float* __restrict__ resid = args.resid[z];
    float* __restrict__ C = args.C[z];
    unsigned* __restrict__ Ctf = args.Ctf[z];
    const int K = args.K[z];
    const int T = K >> 5;

    const int m0 = blockIdx.y * 128;
    const int n0 = blockIdx.x * 128;

    const int tid  = threadIdx.x;
    const int lane = tid & 31;
    const int wid  = tid >> 5;
    const int wm   = (wid & 3) * 32;     // warp M offset
    const int wn   = (wid >> 2) * 64;    // warp N offset (2 warps cover 128)
    const int g    = lane >> 2;
    const int tg   = lane & 3;

    const int rl = tid >> 3;
    const int ql = tid & 7;

    const unsigned smem_base = (unsigned)__cvta_generic_to_shared(smem_dyn);
    const unsigned sA0 = smem_base;                       // A tiles
    const unsigned sW0 = smem_base + NSTAGE * A_TW * 4;   // W tiles

    const unsigned dA = sA0 + (rl * 36 + ql * 4) * 4;
    const unsigned dW = sW0 + (rl * 36 + ql * 4) * 4;

    // ldmatrix per-thread offsets (bytes, within a tile)
    const int matA = lane >> 3;       // matrix index 0..3
    const int rin  = lane & 7;        // row within matrix
    unsigned offA[2];
#pragma unroll
    for (int mt = 0; mt < 2; mt++)
        offA[mt] = ((wm + mt * 16 + (matA & 1) * 8 + rin) * 36 + (matA >> 1) * 4) * 4;
    // B pairs p=0..3: nt = p*2 + (mat>>1), khalf = mat&1
    unsigned offB[4];
#pragma unroll
    for (int p = 0; p < 4; p++)
        offB[p] = ((wn + (p * 2 + (matA >> 1)) * 8 + rin) * 36 + (matA & 1) * 4) * 4;

    float acc[2][8][4];
#pragma unroll
    for (int mt = 0; mt < 2; mt++)
#pragma unroll
        for (int nt = 0; nt < 8; nt++)
#pragma unroll
            for (int r = 0; r < 4; r++) acc[mt][nt][r] = 0.f;

    auto issue = [&](int t, int st) {
        const int k0 = t * 32 + ql * 4;
        const unsigned soffA = dA + st * A_TW * 4;
        const unsigned soffW = dW + st * W_TW * 4;
#pragma unroll
        for (int it = 0; it < 4; it++)
            cp_async16(soffA + it * 32 * 36 * 4, A + (m0 + rl + it * 32) * K + k0);
#pragma unroll
        for (int it = 0; it < 4; it++)
            cp_async16(soffW + it * 32 * 36 * 4, W + (n0 + rl + it * 32) * K + k0);
    };

    issue(0, 0); cp_commit();
    if (T > 1) issue(1, 1);
    cp_commit();

    int st = 0;
    for (int t = 0; t < T; t++) {
        cp_wait1();
        __syncthreads();

        if (t + 2 < T) issue(t + 2, (st + 2) % NSTAGE);
        cp_commit();

        const unsigned aBase = sA0 + st * A_TW * 4;
        const unsigned wBase = sW0 + st * W_TW * 4;

#pragma unroll
        for (int ks = 0; ks < 4; ks++) {
            const unsigned kbB = ks * 8 * 4;
            unsigned a[2][4], b[8][2];
#pragma unroll
            for (int mt = 0; mt < 2; mt++)
                ldsm_x4(a[mt][0], a[mt][1], a[mt][2], a[mt][3], aBase + offA[mt] + kbB);
#pragma unroll
            for (int p = 0; p < 4; p++)
                ldsm_x4(b[p * 2][0], b[p * 2][1], b[p * 2 + 1][0], b[p * 2 + 1][1],
                        wBase + offB[p] + kbB);
#pragma unroll
            for (int mt = 0; mt < 2; mt++)
#pragma unroll
                for (int nt = 0; nt < 8; nt++) {
                    asm volatile(
                        "mma.sync.aligned.m16n8k8.row.col.f32.tf32.tf32.f32 "
                        "{%0,%1,%2,%3}, {%4,%5,%6,%7}, {%8,%9}, {%0,%1,%2,%3};"
                        : "+f"(acc[mt][nt][0]), "+f"(acc[mt][nt][1]),
                          "+f"(acc[mt][nt][2]), "+f"(acc[mt][nt][3])
                        : "r"(a[mt][0]), "r"(a[mt][1]), "r"(a[mt][2]), "r"(a[mt][3]),
                          "r"(b[nt][0]), "r"(b[nt][1]));
                }
        }
        st = (st + 1) % NSTAGE;
    }

#pragma unroll
    for (int mt = 0; mt < 2; mt++) {
#pragma unroll
        for (int nt = 0; nt < 8; nt++) {
            int row0 = m0 + wm + mt * 16 + g;
            int col  = n0 + wn + nt * 8 + tg * 2;
            float b0 = bias[col], b1 = bias[col + 1];
            float2 v0 = make_float2(acc[mt][nt][0] + b0, acc[mt][nt][1] + b1);
            float2 v1 = make_float2(acc[mt][nt][2] + b0, acc[mt][nt][3] + b1);
            if (resid) {
                float2 r0 = *(const float2*)(resid + row0 * DM + col);
                float2 r1 = *(const float2*)(resid + (row0 + 8) * DM + col);
                v0.x += r0.x; v0.y += r0.y;
                v1.x += r1.x; v1.y += r1.y;
            }
            *(float2*)(C + row0 * DM + col)       = v0;
            *(float2*)(C + (row0 + 8) * DM + col) = v1;
            if (Ctf) {
                *(uint2*)(Ctf + row0 * DM + col) = make_uint2(f2tf32(v0.x), f2tf32(v0.y));
                *(uint2*)(Ctf + (row0 + 8) * DM + col) = make_uint2(f2tf32(v1.x), f2tf32(v1.y));
            }
        }
    }
}

// ---------------------------------------------------------------------------
// CTA-tiled sliding-window attention (R10/R13 config, unchanged).
// ---------------------------------------------------------------------------
#define KPAD 133
#define VPAD 136
#define QPAD 136
#define ATT_SMEM ((130 * VPAD + 64 * QPAD + 130 * KPAD) * 4)

extern __shared__ float att_sm[];

__global__ __launch_bounds__(512, 1) void swattn_tiled(
        const float* __restrict__ kb0, const float* __restrict__ vb0,
        const float* __restrict__ kb1, const float* __restrict__ vb1) {
    float* Vs = att_sm;
    float* Qs = att_sm + 130 * VPAD;
    float* Ks = Qs + 64 * QPAD;
    float* S  = Qs;

    const int a  = blockIdx.z;
    const int h  = blockIdx.y;
    const int i0 = blockIdx.x * 64;
    const int idx0 = i0 - 32;
    const int tid = threadIdx.x;

    const float* __restrict__ Qg = g_Q[a];
    const float* __restrict__ Kg = g_K[a];
    const float* __restrict__ Vg = g_V[a];
    const float* __restrict__ kb = (a ? kb1 : kb0) + h * 128;
    const float* __restrict__ vb = (a ? vb1 : vb0) + h * 128;

    const float scale = 0.08838834764831845f;

    for (int f = tid; f < 64 * 32; f += 512) {
        int r = f >> 5, c = f & 31;
        float4 v = *(const float4*)(Qg + (i0 + r) * DM + h * 128 + c * 4);
        *(float4*)(Qs + r * QPAD + c * 4) = v;
    }
    for (int f = tid; f < 130 * 32; f += 512) {
        int j = f >> 5, c = f & 31;
        int gr = min(max(idx0 + j, 0), 511);
        const float* ksrc = (j < 129) ? Kg + gr * DM + h * 128 : kb;
        const float* vsrc = (j < 129) ? Vg + gr * DM + h * 128 : vb;
        float4 kv = *(const float4*)(ksrc + c * 4);
        float4 vv = *(const float4*)(vsrc + c * 4);
        Ks[j * KPAD + c * 4 + 0] = kv.x;
        Ks[j * KPAD + c * 4 + 1] = kv.y;
        Ks[j * KPAD + c * 4 + 2] = kv.z;
        Ks[j * KPAD + c * 4 + 3] = kv.w;
        *(float4*)(Vs + j * VPAD + c * 4) = vv;
    }
    __syncthreads();

    {
        const int ty = tid >> 4;
        const int tx = tid & 15;
        const int qb = ty * 2;

        int  jidx[6];
        bool jok[6];
#pragma unroll
        for (int jj = 0; jj < 5; jj++) {
            jidx[jj] = qb + tx + 16 * jj;
            jok[jj]  = (jidx[jj] < 130);
        }
        jidx[5] = 129; jok[5] = true;

        float acc[2][6];
#pragma unroll
        for (int qq = 0; qq < 2; qq++)
#pragma unroll
            for (int jj = 0; jj < 6; jj++) acc[qq][jj] = 0.f;

#pragma unroll 8
        for (int kk = 0; kk < 128; kk++) {
            float qv[2];
#pragma unroll
            for (int qq = 0; qq < 2; qq++) qv[qq] = Qs[(qb + qq) * QPAD + kk];
#pragma unroll
            for (int jj = 0; jj < 6; jj++) {
                if (jok[jj]) {
                    float kv = Ks[jidx[jj] * KPAD + kk];
#pragma unroll
                    for (int qq = 0; qq < 2; qq++) acc[qq][jj] += qv[qq] * kv;
                }
            }
        }
        __syncthreads();

#pragma unroll
        for (int jj = 0; jj < 6; jj++) {
            if (jok[jj] && (jj < 5 || tx == 0)) {
#pragma unroll
                for (int qq = 0; qq < 2; qq++)
                    S[(qb + qq) * QPAD + jidx[jj]] = acc[qq][jj] * scale;
            }
        }
    }
    __syncthreads();

    {
        const int q = tid >> 3;
        const int s = tid & 7;
        const int i = i0 + q;
        const int p_start = max(0, 32 - i);
        const int p_end   = min(66, 544 - i);
        const int invalid = 66 - (p_end - p_start);
        const int n_pad   = max(0, invalid - 2);

        float vals[9];
        float m = -1e30f;
#pragma unroll
        for (int k = 0; k < 9; k++) {
            int p = s + 8 * k;
            bool valid = (p >= p_start) & (p < p_end);
            vals[k] = valid ? S[q * QPAD + q + p] : -1e30f;
            m = fmaxf(m, vals[k]);
        }
        float sp = S[q * QPAD + 129];
        if (n_pad > 0) m = fmaxf(m, sp);
        m = fmaxf(m, __shfl_xor_sync(0xffffffffu, m, 1));
        m = fmaxf(m, __shfl_xor_sync(0xffffffffu, m, 2));
        m = fmaxf(m, __shfl_xor_sync(0xffffffffu, m, 4));

        float d = 0.f;
#pragma unroll
        for (int k = 0; k < 9; k++) {
            int p = s + 8 * k;
            bool valid = (p >= p_start) & (p < p_end);
            float e = valid ? expf(vals[k] - m) : 0.f;
            vals[k] = e;
            d += e;
        }
        d += __shfl_xor_sync(0xffffffffu, d, 1);
        d += __shfl_xor_sync(0xffffffffu, d, 2);
        d += __shfl_xor_sync(0xffffffffu, d, 4);
        float wp = (n_pad > 0) ? (float)n_pad * expf(sp - m) : 0.f;
        const float inv = 1.f / (d + wp);

        __syncwarp();
        for (int c = s * 17; c < s * 17 + 17; c++) S[q * QPAD + c] = 0.f;
        __syncwarp();

#pragma unroll
        for (int k = 0; k < 9; k++) {
            int p = s + 8 * k;
            if ((p >= p_start) & (p < p_end)) S[q * QPAD + q + p] = vals[k] * inv;
        }
        if (s == 0) S[q * QPAD + 129] = wp * inv;
    }
    __syncthreads();

    {
        const int wty  = tid >> 5;
        const int lane = tid & 31;
        const int qb0  = wty * 4;

        float4 acc[4];
#pragma unroll
        for (int qq = 0; qq < 4; qq++) acc[qq] = make_float4(0.f, 0.f, 0.f, 0.f);

        for (int j = qb0; j <= qb0 + 68; j++) {
            float4 v4 = *(const float4*)(Vs + j * VPAD + lane * 4);
#pragma unroll
            for (int qq = 0; qq < 4; qq++) {
                float w = S[(qb0 + qq) * QPAD + j];
                acc[qq].x += w * v4.x; acc[qq].y += w * v4.y;
                acc[qq].z += w * v4.z; acc[qq].w += w * v4.w;
            }
        }
        {
            float4 v4 = *(const float4*)(Vs + 129 * VPAD + lane * 4);
#pragma unroll
            for (int qq = 0; qq < 4; qq++) {
                float w = S[(qb0 + qq) * QPAD + 129];
                acc[qq].x += w * v4.x; acc[qq].y += w * v4.y;
                acc[qq].z += w * v4.z; acc[qq].w += w * v4.w;
            }
        }
#pragma unroll
        for (int qq = 0; qq < 4; qq++) {
            *(uint4*)(g_O_tf[a] + (i0 + qb0 + qq) * DM + h * 128 + lane * 4) = cvt4(acc[qq]);
        }
    }
}

// ---------------------------------------------------------------------------
extern "C" void kernel_launch(void* const* d_in, const int* in_sizes, int n_in,
                              void* d_out, int out_size) {
    (void)in_sizes; (void)n_in; (void)out_size;

    const float* images   = (const float*)d_in[0];
    const float* captions = (const float*)d_in[1];
    const float* tp_w = (const float*)d_in[3];
    const float* tp_b = (const float*)d_in[4];
    const float* ip_w = (const float*)d_in[5];
    const float* ip_b = (const float*)d_in[6];
    const float* ia[8]; for (int k = 0; k < 8; k++) ia[k] = (const float*)d_in[7 + k];
    const float* ta[8]; for (int k = 0; k < 8; k++) ta[k] = (const float*)d_in[15 + k];
    float* out = (float*)d_out;

    float *txt, *img, *Qb, *Kb, *Vb;
    unsigned *txt_tf, *img_tf, *Otf, *wtf, *cap_tf, *im_tf;
    cudaGetSymbolAddress((void**)&txt, g_txt);
    cudaGetSymbolAddress((void**)&img, g_img);
    cudaGetSymbolAddress((void**)&txt_tf, g_txt_tf);
    cudaGetSymbolAddress((void**)&img_tf, g_img_tf);
    cudaGetSymbolAddress((void**)&Qb, g_Q);
    cudaGetSymbolAddress((void**)&Kb, g_K);
    cudaGetSymbolAddress((void**)&Vb, g_V);
    cudaGetSymbolAddress((void**)&Otf, g_O_tf);
    cudaGetSymbolAddress((void**)&wtf, g_w_tf);
    cudaGetSymbolAddress((void**)&cap_tf, g_cap_tf);
    cudaGetSymbolAddress((void**)&im_tf, g_im_tf);

    unsigned* wts[10];
    for (int s = 0; s < 10; s++) wts[s] = wtf + s * (DM * DM);

    // ---- launch 0: bulk tf32 conversion ----
    {
        ConvArgs ca{};
        const float* srcs[12] = { tp_w, ip_w, ia[0], ia[2], ia[4], ia[6],
                                  ta[0], ta[2], ta[4], ta[6], captions, images };
        unsigned*    dsts[12] = { wts[0], wts[1], wts[2], wts[3], wts[4], wts[5],
                                  wts[6], wts[7], wts[8], wts[9], cap_tf, im_tf };
        int ns[12] = { DM * 768, DM * DM, DM * DM, DM * DM, DM * DM, DM * DM,
                       DM * DM, DM * DM, DM * DM, DM * DM, NQ * 768, NQ * DM };
        for (int s = 0; s < 12; s++) { ca.src[s] = srcs[s]; ca.dst[s] = dsts[s]; ca.n4[s] = ns[s] / 4; }
        conv_tf32_kernel<<<dim3(64, 12), 256>>>(ca);
    }

    const dim3 blk(256);
    const int GX = DM / 128;   // 8
    const int GY = NQ / 128;   // 4
    cudaFuncSetAttribute(gemm_tf32_kernel, cudaFuncAttributeMaxDynamicSharedMemorySize, GEMM_SMEM);
    cudaFuncSetAttribute(swattn_tiled, cudaFuncAttributeMaxDynamicSharedMemorySize, ATT_SMEM);

    // ---- launch 1: input projections (z=2) ----
    {
        GemmArgs ar{};
        ar.A[0] = cap_tf; ar.W[0] = wts[0]; ar.bias[0] = tp_b; ar.resid[0] = nullptr;
        ar.C[0] = txt; ar.Ctf[0] = txt_tf; ar.K[0] = 768;
        ar.A[1] = im_tf;  ar.W[1] = wts[1]; ar.bias[1] = ip_b; ar.resid[1] = nullptr;
        ar.C[1] = img; ar.Ctf[1] = img_tf; ar.K[1] = 1024;
        gemm_tf32_kernel<<<dim3(GX, GY, 2), blk, GEMM_SMEM>>>(ar);
    }

    // ---- launch 2: six QKV projections (z=6) ----
    {
        GemmArgs ar{};
        const unsigned* Aarr[6] = { img_tf, txt_tf, txt_tf, txt_tf, img_tf, img_tf };
        const unsigned* Warr[6] = { wts[2], wts[3], wts[4], wts[6], wts[7], wts[8] };
        const float*    Barr[6] = { ia[1], ia[3], ia[5], ta[1], ta[3], ta[5] };
        float*          Carr[6] = { Qb, Kb, Vb, Qb + NEL, Kb + NEL, Vb + NEL };
        for (int s = 0; s < 6; s++) {
            ar.A[s] = Aarr[s]; ar.W[s] = Warr[s]; ar.bias[s] = Barr[s];
            ar.resid[s] = nullptr; ar.C[s] = Carr[s]; ar.Ctf[s] = nullptr; ar.K[s] = 1024;
        }
        gemm_tf32_kernel<<<dim3(GX, GY, 6), blk, GEMM_SMEM>>>(ar);
    }

    // ---- launch 3: CTA-tiled sliding-window attention (64q tiles) ----
    swattn_tiled<<<dim3(8, 8, 2), 512, ATT_SMEM>>>(ia[3], ia[5], ta[3], ta[5]);

    // ---- launch 4: output projections + residual (z=2) ----
    {
        GemmArgs ar{};
        ar.A[0] = Otf;       ar.W[0] = wts[5]; ar.bias[0] = ia[7]; ar.resid[0] = img;
        ar.C[0] = out;       ar.Ctf[0] = nullptr; ar.K[0] = 1024;
        ar.A[1] = Otf + NEL; ar.W[1] = wts[9]; ar.bias[1] = ta[7]; ar.resid[1] = txt;
        ar.C[1] = out + NEL; ar.Ctf[1] = nullptr; ar.K[1] = 1024;
        gemm_tf32_kernel<<<dim3(GX, GY, 2), blk, GEMM_SMEM>>>(ar);
    }
}

// round 16
// speedup vs baseline: 1.1830x; 1.1830x over previous
#include <cuda_runtime.h>
#include <cuda_bf16.h>
#include <math.h>

#define NQ 512
#define DM 1024
#define NEL (NQ * DM)

// ---------------- scratch ----------------
__device__ float    g_txt[NEL];           // f32 (residual)
__device__ float    g_img[NEL];
__device__ unsigned g_txt_tf[NEL];        // tf32 copies (GEMM A inputs)
__device__ unsigned g_img_tf[NEL];
__device__ float    g_Q[2][NEL];
__device__ float    g_K[2][NEL];
__device__ float    g_V[2][NEL];
__device__ unsigned g_O_tf[2][NEL];       // attention out, tf32
__device__ unsigned g_w_tf[10][DM * DM];
__device__ unsigned g_cap_tf[NQ * 768];
__device__ unsigned g_im_tf[NEL];

__device__ __forceinline__ unsigned f2tf32(float x) {
    unsigned u;
    asm("cvt.rna.tf32.f32 %0, %1;" : "=r"(u) : "f"(x));
    return u;
}
__device__ __forceinline__ uint4 cvt4(float4 v) {
    return make_uint4(f2tf32(v.x), f2tf32(v.y), f2tf32(v.z), f2tf32(v.w));
}

// ---------------- bulk f32 -> tf32 conversion ----------------
struct ConvArgs {
    const float* src[12];
    unsigned*    dst[12];
    int          n4[12];
};

__global__ __launch_bounds__(256) void conv_tf32_kernel(ConvArgs a) {
    const int z = blockIdx.y;
    const float4* __restrict__ s = (const float4*)a.src[z];
    uint4* __restrict__ d = (uint4*)a.dst[z];
    const int n4 = a.n4[z];
    for (int i = blockIdx.x * blockDim.x + threadIdx.x; i < n4; i += gridDim.x * blockDim.x)
        d[i] = cvt4(s[i]);
}

// ---------------------------------------------------------------------------
// tf32 GEMM (pre-converted inputs): C = A(512xK) @ W(1024xK)^T + bias (+resid)
// BM=128, BN=64, BK=32, 256 threads (8 warps, 4Mx2N, warp tile 32x32).
// cp.async 3-stage pipeline; fragment loads via ldmatrix.x4.   (R13 config)
// ---------------------------------------------------------------------------
struct GemmArgs {
    const unsigned* A[6];
    const unsigned* W[6];
    const float*    bias[6];
    const float*    resid[6];
    float*          C[6];
    unsigned*       Ctf[6];
    int             K[6];
};

#define NSTAGE 3
#define A_TW (128 * 36)
#define W_TW (64 * 36)
#define GEMM_SMEM ((A_TW + W_TW) * NSTAGE * 4)

__device__ __forceinline__ void cp_async16(unsigned smem_addr, const void* gptr) {
    asm volatile("cp.async.cg.shared.global [%0], [%1], 16;" :: "r"(smem_addr), "l"(gptr));
}
__device__ __forceinline__ void cp_commit() { asm volatile("cp.async.commit_group;"); }
__device__ __forceinline__ void cp_wait1()  { asm volatile("cp.async.wait_group 1;"); }

__device__ __forceinline__ void ldsm_x4(unsigned& r0, unsigned& r1, unsigned& r2, unsigned& r3,
                                        unsigned addr) {
    asm volatile("ldmatrix.sync.aligned.m8n8.x4.shared.b16 {%0,%1,%2,%3}, [%4];"
                 : "=r"(r0), "=r"(r1), "=r"(r2), "=r"(r3) : "r"(addr));
}

extern __shared__ unsigned smem_dyn[];

__global__ __launch_bounds__(256) void gemm_tf32_kernel(GemmArgs args) {
    const int z = blockIdx.z;
    const unsigned* __restrict__ A = args.A[z];
    const unsigned* __restrict__ W = args.W[z];
    const float* __restrict__ bias = args.bias[z];
    const float* __restrict__ resid = args.resid[z];
    float* __restrict__ C = args.C[z];
    unsigned* __restrict__ Ctf = args.Ctf[z];
    const int K = args.K[z];
    const int T = K >> 5;

    const int m0 = blockIdx.y * 128;
    const int n0 = blockIdx.x * 64;

    const int tid  = threadIdx.x;
    const int lane = tid & 31;
    const int wid  = tid >> 5;
    const int wm   = (wid & 3) * 32;
    const int wn   = (wid >> 2) * 32;
    const int g    = lane >> 2;
    const int tg   = lane & 3;

    const int rl = tid >> 3;
    const int ql = tid & 7;

    const unsigned smem_base = (unsigned)__cvta_generic_to_shared(smem_dyn);
    const unsigned sA0 = smem_base;
    const unsigned sW0 = smem_base + NSTAGE * A_TW * 4;

    const unsigned dA = sA0 + (rl * 36 + ql * 4) * 4;
    const unsigned dW = sW0 + (rl * 36 + ql * 4) * 4;

    const int matA = lane >> 3;
    const int rin  = lane & 7;
    unsigned offA[2];
#pragma unroll
    for (int mt = 0; mt < 2; mt++)
        offA[mt] = ((wm + mt * 16 + (matA & 1) * 8 + rin) * 36 + (matA >> 1) * 4) * 4;
    unsigned offB[2];
#pragma unroll
    for (int p = 0; p < 2; p++)
        offB[p] = ((wn + (p * 2 + (matA >> 1)) * 8 + rin) * 36 + (matA & 1) * 4) * 4;

    float acc[2][4][4];
#pragma unroll
    for (int mt = 0; mt < 2; mt++)
#pragma unroll
        for (int nt = 0; nt < 4; nt++)
#pragma unroll
            for (int r = 0; r < 4; r++) acc[mt][nt][r] = 0.f;

    auto issue = [&](int t, int st) {
        const int k0 = t * 32 + ql * 4;
        const unsigned soffA = dA + st * A_TW * 4;
        const unsigned soffW = dW + st * W_TW * 4;
#pragma unroll
        for (int it = 0; it < 4; it++)
            cp_async16(soffA + it * 32 * 36 * 4, A + (m0 + rl + it * 32) * K + k0);
#pragma unroll
        for (int it = 0; it < 2; it++)
            cp_async16(soffW + it * 32 * 36 * 4, W + (n0 + rl + it * 32) * K + k0);
    };

    issue(0, 0); cp_commit();
    if (T > 1) issue(1, 1);
    cp_commit();

    int st = 0;
    for (int t = 0; t < T; t++) {
        cp_wait1();
        __syncthreads();

        if (t + 2 < T) issue(t + 2, (st + 2) % NSTAGE);
        cp_commit();

        const unsigned aBase = sA0 + st * A_TW * 4;
        const unsigned wBase = sW0 + st * W_TW * 4;

#pragma unroll
        for (int ks = 0; ks < 4; ks++) {
            const unsigned kbB = ks * 8 * 4;
            unsigned a[2][4], b[4][2];
#pragma unroll
            for (int mt = 0; mt < 2; mt++)
                ldsm_x4(a[mt][0], a[mt][1], a[mt][2], a[mt][3], aBase + offA[mt] + kbB);
#pragma unroll
            for (int p = 0; p < 2; p++)
                ldsm_x4(b[p * 2][0], b[p * 2][1], b[p * 2 + 1][0], b[p * 2 + 1][1],
                        wBase + offB[p] + kbB);
#pragma unroll
            for (int mt = 0; mt < 2; mt++)
#pragma unroll
                for (int nt = 0; nt < 4; nt++) {
                    asm volatile(
                        "mma.sync.aligned.m16n8k8.row.col.f32.tf32.tf32.f32 "
                        "{%0,%1,%2,%3}, {%4,%5,%6,%7}, {%8,%9}, {%0,%1,%2,%3};"
                        : "+f"(acc[mt][nt][0]), "+f"(acc[mt][nt][1]),
                          "+f"(acc[mt][nt][2]), "+f"(acc[mt][nt][3])
                        : "r"(a[mt][0]), "r"(a[mt][1]), "r"(a[mt][2]), "r"(a[mt][3]),
                          "r"(b[nt][0]), "r"(b[nt][1]));
                }
        }
        st = (st + 1) % NSTAGE;
    }

#pragma unroll
    for (int mt = 0; mt < 2; mt++) {
#pragma unroll
        for (int nt = 0; nt < 4; nt++) {
            int row0 = m0 + wm + mt * 16 + g;
            int col  = n0 + wn + nt * 8 + tg * 2;
            float b0 = bias[col], b1 = bias[col + 1];
            float2 v0 = make_float2(acc[mt][nt][0] + b0, acc[mt][nt][1] + b1);
            float2 v1 = make_float2(acc[mt][nt][2] + b0, acc[mt][nt][3] + b1);
            if (resid) {
                float2 r0 = *(const float2*)(resid + row0 * DM + col);
                float2 r1 = *(const float2*)(resid + (row0 + 8) * DM + col);
                v0.x += r0.x; v0.y += r0.y;
                v1.x += r1.x; v1.y += r1.y;
            }
            *(float2*)(C + row0 * DM + col)       = v0;
            *(float2*)(C + (row0 + 8) * DM + col) = v1;
            if (Ctf) {
                *(uint2*)(Ctf + row0 * DM + col) = make_uint2(f2tf32(v0.x), f2tf32(v0.y));
                *(uint2*)(Ctf + (row0 + 8) * DM + col) = make_uint2(f2tf32(v1.x), f2tf32(v1.y));
            }
        }
    }
}

// ---------------------------------------------------------------------------
// CTA-tiled sliding-window attention, 64 queries/CTA, 512 thr.
// V is NOT staged: V phase reads rows directly from global (L1-resident).
// Smem = Qs/S[64][136] + Ks[130][133] = 103,976 B -> 2 CTAs/SM.
// ---------------------------------------------------------------------------
#define KPAD 133
#define QPAD 136
#define ATT_SMEM ((64 * QPAD + 130 * KPAD) * 4)

extern __shared__ float att_sm[];

__global__ __launch_bounds__(512, 2) void swattn_tiled(
        const float* __restrict__ kb0, const float* __restrict__ vb0,
        const float* __restrict__ kb1, const float* __restrict__ vb1) {
    float* Qs = att_sm;                        // [64][136] (float4, aligned)
    float* Ks = att_sm + 64 * QPAD;            // [130][133] (scalar only)
    float* S  = Qs;

    const int a  = blockIdx.z;
    const int h  = blockIdx.y;
    const int i0 = blockIdx.x * 64;
    const int idx0 = i0 - 32;
    const int tid = threadIdx.x;

    const float* __restrict__ Qg = g_Q[a];
    const float* __restrict__ Kg = g_K[a];
    const float* __restrict__ Vg = g_V[a];
    const float* __restrict__ kb = (a ? kb1 : kb0) + h * 128;
    const float* __restrict__ vb = (a ? vb1 : vb0) + h * 128;

    const float scale = 0.08838834764831845f;  // 1/sqrt(128)

    // ---- stage Q (64 x 128) ----
    for (int f = tid; f < 64 * 32; f += 512) {
        int r = f >> 5, c = f & 31;
        float4 v = *(const float4*)(Qg + (i0 + r) * DM + h * 128 + c * 4);
        *(float4*)(Qs + r * QPAD + c * 4) = v;
    }
    // ---- stage K band (j=0..128 real, j=129 = kb) ----
    for (int f = tid; f < 130 * 32; f += 512) {
        int j = f >> 5, c = f & 31;
        int gr = min(max(idx0 + j, 0), 511);
        const float* ksrc = (j < 129) ? Kg + gr * DM + h * 128 : kb;
        float4 kv = *(const float4*)(ksrc + c * 4);
        Ks[j * KPAD + c * 4 + 0] = kv.x;
        Ks[j * KPAD + c * 4 + 1] = kv.y;
        Ks[j * KPAD + c * 4 + 2] = kv.z;
        Ks[j * KPAD + c * 4 + 3] = kv.w;
    }
    __syncthreads();

    // ---- score GEMM (2 queries x 6 j per thread) ----
    {
        const int ty = tid >> 4;
        const int tx = tid & 15;
        const int qb = ty * 2;

        int  jidx[6];
        bool jok[6];
#pragma unroll
        for (int jj = 0; jj < 5; jj++) {
            jidx[jj] = qb + tx + 16 * jj;
            jok[jj]  = (jidx[jj] < 130);
        }
        jidx[5] = 129; jok[5] = true;

        float acc[2][6];
#pragma unroll
        for (int qq = 0; qq < 2; qq++)
#pragma unroll
            for (int jj = 0; jj < 6; jj++) acc[qq][jj] = 0.f;

#pragma unroll 8
        for (int kk = 0; kk < 128; kk++) {
            float qv[2];
#pragma unroll
            for (int qq = 0; qq < 2; qq++) qv[qq] = Qs[(qb + qq) * QPAD + kk];
#pragma unroll
            for (int jj = 0; jj < 6; jj++) {
                if (jok[jj]) {
                    float kv = Ks[jidx[jj] * KPAD + kk];
#pragma unroll
                    for (int qq = 0; qq < 2; qq++) acc[qq][jj] += qv[qq] * kv;
                }
            }
        }
        __syncthreads();  // done reading Qs; S aliases it

#pragma unroll
        for (int jj = 0; jj < 6; jj++) {
            if (jok[jj] && (jj < 5 || tx == 0)) {
#pragma unroll
                for (int qq = 0; qq < 2; qq++)
                    S[(qb + qq) * QPAD + jidx[jj]] = acc[qq][jj] * scale;
            }
        }
    }
    __syncthreads();

    // ---- softmax per query (8 threads per query) ----
    {
        const int q = tid >> 3;
        const int s = tid & 7;
        const int i = i0 + q;
        const int p_start = max(0, 32 - i);
        const int p_end   = min(66, 544 - i);
        const int invalid = 66 - (p_end - p_start);
        const int n_pad   = max(0, invalid - 2);

        float vals[9];
        float m = -1e30f;
#pragma unroll
        for (int k = 0; k < 9; k++) {
            int p = s + 8 * k;
            bool valid = (p >= p_start) & (p < p_end);
            vals[k] = valid ? S[q * QPAD + q + p] : -1e30f;
            m = fmaxf(m, vals[k]);
        }
        float sp = S[q * QPAD + 129];
        if (n_pad > 0) m = fmaxf(m, sp);
        m = fmaxf(m, __shfl_xor_sync(0xffffffffu, m, 1));
        m = fmaxf(m, __shfl_xor_sync(0xffffffffu, m, 2));
        m = fmaxf(m, __shfl_xor_sync(0xffffffffu, m, 4));

        float d = 0.f;
#pragma unroll
        for (int k = 0; k < 9; k++) {
            int p = s + 8 * k;
            bool valid = (p >= p_start) & (p < p_end);
            float e = valid ? expf(vals[k] - m) : 0.f;
            vals[k] = e;
            d += e;
        }
        d += __shfl_xor_sync(0xffffffffu, d, 1);
        d += __shfl_xor_sync(0xffffffffu, d, 2);
        d += __shfl_xor_sync(0xffffffffu, d, 4);
        float wp = (n_pad > 0) ? (float)n_pad * expf(sp - m) : 0.f;
        const float inv = 1.f / (d + wp);

        __syncwarp();
        for (int c = s * 17; c < s * 17 + 17; c++) S[q * QPAD + c] = 0.f;
        __syncwarp();

#pragma unroll
        for (int k = 0; k < 9; k++) {
            int p = s + 8 * k;
            if ((p >= p_start) & (p < p_end)) S[q * QPAD + q + p] = vals[k] * inv;
        }
        if (s == 0) S[q * QPAD + 129] = wp * inv;
    }
    __syncthreads();

    // ---- V phase: warp per 4 queries, V rows read from GLOBAL ----
    {
        const int wty  = tid >> 5;
        const int lane = tid & 31;
        const int qb0  = wty * 4;

        float4 acc[4];
#pragma unroll
        for (int qq = 0; qq < 4; qq++) acc[qq] = make_float4(0.f, 0.f, 0.f, 0.f);

        for (int j = qb0; j <= qb0 + 68; j++) {   // j <= 128 always
            int gr = min(max(idx0 + j, 0), 511);
            float4 v4 = *(const float4*)(Vg + gr * DM + h * 128 + lane * 4);
#pragma unroll
            for (int qq = 0; qq < 4; qq++) {
                float w = S[(qb0 + qq) * QPAD + j];
                acc[qq].x += w * v4.x; acc[qq].y += w * v4.y;
                acc[qq].z += w * v4.z; acc[qq].w += w * v4.w;
            }
        }
        {   // pad row (weights at col 129)
            float4 v4 = *(const float4*)(vb + lane * 4);
#pragma unroll
            for (int qq = 0; qq < 4; qq++) {
                float w = S[(qb0 + qq) * QPAD + 129];
                acc[qq].x += w * v4.x; acc[qq].y += w * v4.y;
                acc[qq].z += w * v4.z; acc[qq].w += w * v4.w;
            }
        }
#pragma unroll
        for (int qq = 0; qq < 4; qq++) {
            *(uint4*)(g_O_tf[a] + (i0 + qb0 + qq) * DM + h * 128 + lane * 4) = cvt4(acc[qq]);
        }
    }
}

// ---------------------------------------------------------------------------
extern "C" void kernel_launch(void* const* d_in, const int* in_sizes, int n_in,
                              void* d_out, int out_size) {
    (void)in_sizes; (void)n_in; (void)out_size;

    const float* images   = (const float*)d_in[0];
    const float* captions = (const float*)d_in[1];
    const float* tp_w = (const float*)d_in[3];
    const float* tp_b = (const float*)d_in[4];
    const float* ip_w = (const float*)d_in[5];
    const float* ip_b = (const float*)d_in[6];
    const float* ia[8]; for (int k = 0; k < 8; k++) ia[k] = (const float*)d_in[7 + k];
    const float* ta[8]; for (int k = 0; k < 8; k++) ta[k] = (const float*)d_in[15 + k];
    float* out = (float*)d_out;

    float *txt, *img, *Qb, *Kb, *Vb;
    unsigned *txt_tf, *img_tf, *Otf, *wtf, *cap_tf, *im_tf;
    cudaGetSymbolAddress((void**)&txt, g_txt);
    cudaGetSymbolAddress((void**)&img, g_img);
    cudaGetSymbolAddress((void**)&txt_tf, g_txt_tf);
    cudaGetSymbolAddress((void**)&img_tf, g_img_tf);
    cudaGetSymbolAddress((void**)&Qb, g_Q);
    cudaGetSymbolAddress((void**)&Kb, g_K);
    cudaGetSymbolAddress((void**)&Vb, g_V);
    cudaGetSymbolAddress((void**)&Otf, g_O_tf);
    cudaGetSymbolAddress((void**)&wtf, g_w_tf);
    cudaGetSymbolAddress((void**)&cap_tf, g_cap_tf);
    cudaGetSymbolAddress((void**)&im_tf, g_im_tf);

    unsigned* wts[10];
    for (int s = 0; s < 10; s++) wts[s] = wtf + s * (DM * DM);

    // ---- launch 0: bulk tf32 conversion ----
    {
        ConvArgs ca{};
        const float* srcs[12] = { tp_w, ip_w, ia[0], ia[2], ia[4], ia[6],
                                  ta[0], ta[2], ta[4], ta[6], captions, images };
        unsigned*    dsts[12] = { wts[0], wts[1], wts[2], wts[3], wts[4], wts[5],
                                  wts[6], wts[7], wts[8], wts[9], cap_tf, im_tf };
        int ns[12] = { DM * 768, DM * DM, DM * DM, DM * DM, DM * DM, DM * DM,
                       DM * DM, DM * DM, DM * DM, DM * DM, NQ * 768, NQ * DM };
        for (int s = 0; s < 12; s++) { ca.src[s] = srcs[s]; ca.dst[s] = dsts[s]; ca.n4[s] = ns[s] / 4; }
        conv_tf32_kernel<<<dim3(64, 12), 256>>>(ca);
    }

    const dim3 blk(256);
    const int GX = DM / 64;    // 16
    const int GY = NQ / 128;   // 4
    cudaFuncSetAttribute(gemm_tf32_kernel, cudaFuncAttributeMaxDynamicSharedMemorySize, GEMM_SMEM);
    cudaFuncSetAttribute(swattn_tiled, cudaFuncAttributeMaxDynamicSharedMemorySize, ATT_SMEM);

    // ---- launch 1: input projections (z=2) ----
    {
        GemmArgs ar{};
        ar.A[0] = cap_tf; ar.W[0] = wts[0]; ar.bias[0] = tp_b; ar.resid[0] = nullptr;
        ar.C[0] = txt; ar.Ctf[0] = txt_tf; ar.K[0] = 768;
        ar.A[1] = im_tf;  ar.W[1] = wts[1]; ar.bias[1] = ip_b; ar.resid[1] = nullptr;
        ar.C[1] = img; ar.Ctf[1] = img_tf; ar.K[1] = 1024;
        gemm_tf32_kernel<<<dim3(GX, GY, 2), blk, GEMM_SMEM>>>(ar);
    }

    // ---- launch 2: six QKV projections (z=6) ----
    {
        GemmArgs ar{};
        const unsigned* Aarr[6] = { img_tf, txt_tf, txt_tf, txt_tf, img_tf, img_tf };
        const unsigned* Warr[6] = { wts[2], wts[3], wts[4], wts[6], wts[7], wts[8] };
        const float*    Barr[6] = { ia[1], ia[3], ia[5], ta[1], ta[3], ta[5] };
        float*          Carr[6] = { Qb, Kb, Vb, Qb + NEL, Kb + NEL, Vb + NEL };
        for (int s = 0; s < 6; s++) {
            ar.A[s] = Aarr[s]; ar.W[s] = Warr[s]; ar.bias[s] = Barr[s];
            ar.resid[s] = nullptr; ar.C[s] = Carr[s]; ar.Ctf[s] = nullptr; ar.K[s] = 1024;
        }
        gemm_tf32_kernel<<<dim3(GX, GY, 6), blk, GEMM_SMEM>>>(ar);
    }

    // ---- launch 3: CTA-tiled sliding-window attention (V from global) ----
    swattn_tiled<<<dim3(8, 8, 2), 512, ATT_SMEM>>>(ia[3], ia[5], ta[3], ta[5]);

    // ---- launch 4: output projections + residual (z=2) ----
    {
        GemmArgs ar{};
        ar.A[0] = Otf;       ar.W[0] = wts[5]; ar.bias[0] = ia[7]; ar.resid[0] = img;
        ar.C[0] = out;       ar.Ctf[0] = nullptr; ar.K[0] = 1024;
        ar.A[1] = Otf + NEL; ar.W[1] = wts[9]; ar.bias[1] = ta[7]; ar.resid[1] = txt;
        ar.C[1] = out + NEL; ar.Ctf[1] = nullptr; ar.K[1] = 1024;
        gemm_tf32_kernel<<<dim3(GX, GY, 2), blk, GEMM_SMEM>>>(ar);
    }
}

// round 17
// speedup vs baseline: 1.3786x; 1.1654x over previous
#include <cuda_runtime.h>
#include <cuda_bf16.h>
#include <math.h>

#define NQ 512
#define DM 1024
#define NEL (NQ * DM)

// ---------------- scratch ----------------
__device__ float    g_txt[NEL];           // f32 (residual)
__device__ float    g_img[NEL];
__device__ unsigned g_txt_tf[NEL];        // tf32 copies (GEMM A inputs, rna-rounded)
__device__ unsigned g_img_tf[NEL];
__device__ float    g_Q[2][NEL];
__device__ float    g_K[2][NEL];
__device__ float    g_V[2][NEL];
__device__ unsigned g_O_tf[2][NEL];       // attention out, tf32

__device__ __forceinline__ unsigned f2tf32(float x) {
    unsigned u;
    asm("cvt.rna.tf32.f32 %0, %1;" : "=r"(u) : "f"(x));
    return u;
}
__device__ __forceinline__ uint4 cvt4(float4 v) {
    return make_uint4(f2tf32(v.x), f2tf32(v.y), f2tf32(v.z), f2tf32(v.w));
}

// ---------------------------------------------------------------------------
// tf32 GEMM: C = A(512xK) @ W(1024xK)^T + bias (+resid)
// A/W are 32-bit operands for mma.tf32 — raw f32 bits are valid (HW ignores
// low mantissa bits; truncation vs rna adds ~1e-4-scale error, within gate).
// BM=128, BN=64, BK=32, 256 threads (8 warps, 4Mx2N, warp tile 32x32).
// cp.async 3-stage pipeline; fragment loads via ldmatrix.x4.   (R13 config)
// ---------------------------------------------------------------------------
struct GemmArgs {
    const unsigned* A[6];
    const unsigned* W[6];
    const float*    bias[6];
    const float*    resid[6];
    float*          C[6];
    unsigned*       Ctf[6];
    int             K[6];
};

#define NSTAGE 3
#define A_TW (128 * 36)
#define W_TW (64 * 36)
#define GEMM_SMEM ((A_TW + W_TW) * NSTAGE * 4)

__device__ __forceinline__ void cp_async16(unsigned smem_addr, const void* gptr) {
    asm volatile("cp.async.cg.shared.global [%0], [%1], 16;" :: "r"(smem_addr), "l"(gptr));
}
__device__ __forceinline__ void cp_commit() { asm volatile("cp.async.commit_group;"); }
__device__ __forceinline__ void cp_wait1()  { asm volatile("cp.async.wait_group 1;"); }

__device__ __forceinline__ void ldsm_x4(unsigned& r0, unsigned& r1, unsigned& r2, unsigned& r3,
                                        unsigned addr) {
    asm volatile("ldmatrix.sync.aligned.m8n8.x4.shared.b16 {%0,%1,%2,%3}, [%4];"
                 : "=r"(r0), "=r"(r1), "=r"(r2), "=r"(r3) : "r"(addr));
}

extern __shared__ unsigned smem_dyn[];

__global__ __launch_bounds__(256) void gemm_tf32_kernel(GemmArgs args) {
    const int z = blockIdx.z;
    const unsigned* __restrict__ A = args.A[z];
    const unsigned* __restrict__ W = args.W[z];
    const float* __restrict__ bias = args.bias[z];
    const float* __restrict__ resid = args.resid[z];
    float* __restrict__ C = args.C[z];
    unsigned* __restrict__ Ctf = args.Ctf[z];
    const int K = args.K[z];
    const int T = K >> 5;

    const int m0 = blockIdx.y * 128;
    const int n0 = blockIdx.x * 64;

    const int tid  = threadIdx.x;
    const int lane = tid & 31;
    const int wid  = tid >> 5;
    const int wm   = (wid & 3) * 32;
    const int wn   = (wid >> 2) * 32;
    const int g    = lane >> 2;
    const int tg   = lane & 3;

    const int rl = tid >> 3;
    const int ql = tid & 7;

    const unsigned smem_base = (unsigned)__cvta_generic_to_shared(smem_dyn);
    const unsigned sA0 = smem_base;
    const unsigned sW0 = smem_base + NSTAGE * A_TW * 4;

    const unsigned dA = sA0 + (rl * 36 + ql * 4) * 4;
    const unsigned dW = sW0 + (rl * 36 + ql * 4) * 4;

    const int matA = lane >> 3;
    const int rin  = lane & 7;
    unsigned offA[2];
#pragma unroll
    for (int mt = 0; mt < 2; mt++)
        offA[mt] = ((wm + mt * 16 + (matA & 1) * 8 + rin) * 36 + (matA >> 1) * 4) * 4;
    unsigned offB[2];
#pragma unroll
    for (int p = 0; p < 2; p++)
        offB[p] = ((wn + (p * 2 + (matA >> 1)) * 8 + rin) * 36 + (matA & 1) * 4) * 4;

    float acc[2][4][4];
#pragma unroll
    for (int mt = 0; mt < 2; mt++)
#pragma unroll
        for (int nt = 0; nt < 4; nt++)
#pragma unroll
            for (int r = 0; r < 4; r++) acc[mt][nt][r] = 0.f;

    auto issue = [&](int t, int st) {
        const int k0 = t * 32 + ql * 4;
        const unsigned soffA = dA + st * A_TW * 4;
        const unsigned soffW = dW + st * W_TW * 4;
#pragma unroll
        for (int it = 0; it < 4; it++)
            cp_async16(soffA + it * 32 * 36 * 4, A + (m0 + rl + it * 32) * K + k0);
#pragma unroll
        for (int it = 0; it < 2; it++)
            cp_async16(soffW + it * 32 * 36 * 4, W + (n0 + rl + it * 32) * K + k0);
    };

    issue(0, 0); cp_commit();
    if (T > 1) issue(1, 1);
    cp_commit();

    int st = 0;
    for (int t = 0; t < T; t++) {
        cp_wait1();
        __syncthreads();

        if (t + 2 < T) issue(t + 2, (st + 2) % NSTAGE);
        cp_commit();

        const unsigned aBase = sA0 + st * A_TW * 4;
        const unsigned wBase = sW0 + st * W_TW * 4;

#pragma unroll
        for (int ks = 0; ks < 4; ks++) {
            const unsigned kbB = ks * 8 * 4;
            unsigned a[2][4], b[4][2];
#pragma unroll
            for (int mt = 0; mt < 2; mt++)
                ldsm_x4(a[mt][0], a[mt][1], a[mt][2], a[mt][3], aBase + offA[mt] + kbB);
#pragma unroll
            for (int p = 0; p < 2; p++)
                ldsm_x4(b[p * 2][0], b[p * 2][1], b[p * 2 + 1][0], b[p * 2 + 1][1],
                        wBase + offB[p] + kbB);
#pragma unroll
            for (int mt = 0; mt < 2; mt++)
#pragma unroll
                for (int nt = 0; nt < 4; nt++) {
                    asm volatile(
                        "mma.sync.aligned.m16n8k8.row.col.f32.tf32.tf32.f32 "
                        "{%0,%1,%2,%3}, {%4,%5,%6,%7}, {%8,%9}, {%0,%1,%2,%3};"
                        : "+f"(acc[mt][nt][0]), "+f"(acc[mt][nt][1]),
                          "+f"(acc[mt][nt][2]), "+f"(acc[mt][nt][3])
                        : "r"(a[mt][0]), "r"(a[mt][1]), "r"(a[mt][2]), "r"(a[mt][3]),
                          "r"(b[nt][0]), "r"(b[nt][1]));
                }
        }
        st = (st + 1) % NSTAGE;
    }

#pragma unroll
    for (int mt = 0; mt < 2; mt++) {
#pragma unroll
        for (int nt = 0; nt < 4; nt++) {
            int row0 = m0 + wm + mt * 16 + g;
            int col  = n0 + wn + nt * 8 + tg * 2;
            float b0 = bias[col], b1 = bias[col + 1];
            float2 v0 = make_float2(acc[mt][nt][0] + b0, acc[mt][nt][1] + b1);
            float2 v1 = make_float2(acc[mt][nt][2] + b0, acc[mt][nt][3] + b1);
            if (resid) {
                float2 r0 = *(const float2*)(resid + row0 * DM + col);
                float2 r1 = *(const float2*)(resid + (row0 + 8) * DM + col);
                v0.x += r0.x; v0.y += r0.y;
                v1.x += r1.x; v1.y += r1.y;
            }
            *(float2*)(C + row0 * DM + col)       = v0;
            *(float2*)(C + (row0 + 8) * DM + col) = v1;
            if (Ctf) {
                *(uint2*)(Ctf + row0 * DM + col) = make_uint2(f2tf32(v0.x), f2tf32(v0.y));
                *(uint2*)(Ctf + (row0 + 8) * DM + col) = make_uint2(f2tf32(v1.x), f2tf32(v1.y));
            }
        }
    }
}

// ---------------------------------------------------------------------------
// CTA-tiled sliding-window attention (R13 config: 64 queries/CTA, 512 thr).
// ---------------------------------------------------------------------------
#define KPAD 133
#define VPAD 136
#define QPAD 136
#define ATT_SMEM ((130 * VPAD + 64 * QPAD + 130 * KPAD) * 4)

extern __shared__ float att_sm[];

__global__ __launch_bounds__(512, 1) void swattn_tiled(
        const float* __restrict__ kb0, const float* __restrict__ vb0,
        const float* __restrict__ kb1, const float* __restrict__ vb1) {
    float* Vs = att_sm;
    float* Qs = att_sm + 130 * VPAD;
    float* Ks = Qs + 64 * QPAD;
    float* S  = Qs;

    const int a  = blockIdx.z;
    const int h  = blockIdx.y;
    const int i0 = blockIdx.x * 64;
    const int idx0 = i0 - 32;
    const int tid = threadIdx.x;

    const float* __restrict__ Qg = g_Q[a];
    const float* __restrict__ Kg = g_K[a];
    const float* __restrict__ Vg = g_V[a];
    const float* __restrict__ kb = (a ? kb1 : kb0) + h * 128;
    const float* __restrict__ vb = (a ? vb1 : vb0) + h * 128;

    const float scale = 0.08838834764831845f;

    for (int f = tid; f < 64 * 32; f += 512) {
        int r = f >> 5, c = f & 31;
        float4 v = *(const float4*)(Qg + (i0 + r) * DM + h * 128 + c * 4);
        *(float4*)(Qs + r * QPAD + c * 4) = v;
    }
    for (int f = tid; f < 130 * 32; f += 512) {
        int j = f >> 5, c = f & 31;
        int gr = min(max(idx0 + j, 0), 511);
        const float* ksrc = (j < 129) ? Kg + gr * DM + h * 128 : kb;
        const float* vsrc = (j < 129) ? Vg + gr * DM + h * 128 : vb;
        float4 kv = *(const float4*)(ksrc + c * 4);
        float4 vv = *(const float4*)(vsrc + c * 4);
        Ks[j * KPAD + c * 4 + 0] = kv.x;
        Ks[j * KPAD + c * 4 + 1] = kv.y;
        Ks[j * KPAD + c * 4 + 2] = kv.z;
        Ks[j * KPAD + c * 4 + 3] = kv.w;
        *(float4*)(Vs + j * VPAD + c * 4) = vv;
    }
    __syncthreads();

    {
        const int ty = tid >> 4;
        const int tx = tid & 15;
        const int qb = ty * 2;

        int  jidx[6];
        bool jok[6];
#pragma unroll
        for (int jj = 0; jj < 5; jj++) {
            jidx[jj] = qb + tx + 16 * jj;
            jok[jj]  = (jidx[jj] < 130);
        }
        jidx[5] = 129; jok[5] = true;

        float acc[2][6];
#pragma unroll
        for (int qq = 0; qq < 2; qq++)
#pragma unroll
            for (int jj = 0; jj < 6; jj++) acc[qq][jj] = 0.f;

#pragma unroll 8
        for (int kk = 0; kk < 128; kk++) {
            float qv[2];
#pragma unroll
            for (int qq = 0; qq < 2; qq++) qv[qq] = Qs[(qb + qq) * QPAD + kk];
#pragma unroll
            for (int jj = 0; jj < 6; jj++) {
                if (jok[jj]) {
                    float kv = Ks[jidx[jj] * KPAD + kk];
#pragma unroll
                    for (int qq = 0; qq < 2; qq++) acc[qq][jj] += qv[qq] * kv;
                }
            }
        }
        __syncthreads();

#pragma unroll
        for (int jj = 0; jj < 6; jj++) {
            if (jok[jj] && (jj < 5 || tx == 0)) {
#pragma unroll
                for (int qq = 0; qq < 2; qq++)
                    S[(qb + qq) * QPAD + jidx[jj]] = acc[qq][jj] * scale;
            }
        }
    }
    __syncthreads();

    {
        const int q = tid >> 3;
        const int s = tid & 7;
        const int i = i0 + q;
        const int p_start = max(0, 32 - i);
        const int p_end   = min(66, 544 - i);
        const int invalid = 66 - (p_end - p_start);
        const int n_pad   = max(0, invalid - 2);

        float vals[9];
        float m = -1e30f;
#pragma unroll
        for (int k = 0; k < 9; k++) {
            int p = s + 8 * k;
            bool valid = (p >= p_start) & (p < p_end);
            vals[k] = valid ? S[q * QPAD + q + p] : -1e30f;
            m = fmaxf(m, vals[k]);
        }
        float sp = S[q * QPAD + 129];
        if (n_pad > 0) m = fmaxf(m, sp);
        m = fmaxf(m, __shfl_xor_sync(0xffffffffu, m, 1));
        m = fmaxf(m, __shfl_xor_sync(0xffffffffu, m, 2));
        m = fmaxf(m, __shfl_xor_sync(0xffffffffu, m, 4));

        float d = 0.f;
#pragma unroll
        for (int k = 0; k < 9; k++) {
            int p = s + 8 * k;
            bool valid = (p >= p_start) & (p < p_end);
            float e = valid ? expf(vals[k] - m) : 0.f;
            vals[k] = e;
            d += e;
        }
        d += __shfl_xor_sync(0xffffffffu, d, 1);
        d += __shfl_xor_sync(0xffffffffu, d, 2);
        d += __shfl_xor_sync(0xffffffffu, d, 4);
        float wp = (n_pad > 0) ? (float)n_pad * expf(sp - m) : 0.f;
        const float inv = 1.f / (d + wp);

        __syncwarp();
        for (int c = s * 17; c < s * 17 + 17; c++) S[q * QPAD + c] = 0.f;
        __syncwarp();

#pragma unroll
        for (int k = 0; k < 9; k++) {
            int p = s + 8 * k;
            if ((p >= p_start) & (p < p_end)) S[q * QPAD + q + p] = vals[k] * inv;
        }
        if (s == 0) S[q * QPAD + 129] = wp * inv;
    }
    __syncthreads();

    {
        const int wty  = tid >> 5;
        const int lane = tid & 31;
        const int qb0  = wty * 4;

        float4 acc[4];
#pragma unroll
        for (int qq = 0; qq < 4; qq++) acc[qq] = make_float4(0.f, 0.f, 0.f, 0.f);

        for (int j = qb0; j <= qb0 + 68; j++) {
            float4 v4 = *(const float4*)(Vs + j * VPAD + lane * 4);
#pragma unroll
            for (int qq = 0; qq < 4; qq++) {
                float w = S[(qb0 + qq) * QPAD + j];
                acc[qq].x += w * v4.x; acc[qq].y += w * v4.y;
                acc[qq].z += w * v4.z; acc[qq].w += w * v4.w;
            }
        }
        {
            float4 v4 = *(const float4*)(Vs + 129 * VPAD + lane * 4);
#pragma unroll
            for (int qq = 0; qq < 4; qq++) {
                float w = S[(qb0 + qq) * QPAD + 129];
                acc[qq].x += w * v4.x; acc[qq].y += w * v4.y;
                acc[qq].z += w * v4.z; acc[qq].w += w * v4.w;
            }
        }
#pragma unroll
        for (int qq = 0; qq < 4; qq++) {
            *(uint4*)(g_O_tf[a] + (i0 + qb0 + qq) * DM + h * 128 + lane * 4) = cvt4(acc[qq]);
        }
    }
}

// ---------------------------------------------------------------------------
extern "C" void kernel_launch(void* const* d_in, const int* in_sizes, int n_in,
                              void* d_out, int out_size) {
    (void)in_sizes; (void)n_in; (void)out_size;

    const float* images   = (const float*)d_in[0];
    const float* captions = (const float*)d_in[1];
    const float* tp_w = (const float*)d_in[3];
    const float* tp_b = (const float*)d_in[4];
    const float* ip_w = (const float*)d_in[5];
    const float* ip_b = (const float*)d_in[6];
    const float* ia[8]; for (int k = 0; k < 8; k++) ia[k] = (const float*)d_in[7 + k];
    const float* ta[8]; for (int k = 0; k < 8; k++) ta[k] = (const float*)d_in[15 + k];
    float* out = (float*)d_out;

    float *txt, *img, *Qb, *Kb, *Vb;
    unsigned *txt_tf, *img_tf, *Otf;
    cudaGetSymbolAddress((void**)&txt, g_txt);
    cudaGetSymbolAddress((void**)&img, g_img);
    cudaGetSymbolAddress((void**)&txt_tf, g_txt_tf);
    cudaGetSymbolAddress((void**)&img_tf, g_img_tf);
    cudaGetSymbolAddress((void**)&Qb, g_Q);
    cudaGetSymbolAddress((void**)&Kb, g_K);
    cudaGetSymbolAddress((void**)&Vb, g_V);
    cudaGetSymbolAddress((void**)&Otf, g_O_tf);

    const dim3 blk(256);
    const int GX = DM / 64;    // 16
    const int GY = NQ / 128;   // 4
    cudaFuncSetAttribute(gemm_tf32_kernel, cudaFuncAttributeMaxDynamicSharedMemorySize, GEMM_SMEM);
    cudaFuncSetAttribute(swattn_tiled, cudaFuncAttributeMaxDynamicSharedMemorySize, ATT_SMEM);

    // ---- launch 1: input projections (z=2); raw f32 bits as tf32 operands ----
    {
        GemmArgs ar{};
        ar.A[0] = (const unsigned*)captions; ar.W[0] = (const unsigned*)tp_w;
        ar.bias[0] = tp_b; ar.resid[0] = nullptr;
        ar.C[0] = txt; ar.Ctf[0] = txt_tf; ar.K[0] = 768;
        ar.A[1] = (const unsigned*)images;   ar.W[1] = (const unsigned*)ip_w;
        ar.bias[1] = ip_b; ar.resid[1] = nullptr;
        ar.C[1] = img; ar.Ctf[1] = img_tf; ar.K[1] = 1024;
        gemm_tf32_kernel<<<dim3(GX, GY, 2), blk, GEMM_SMEM>>>(ar);
    }

    // ---- launch 2: six QKV projections (z=6) ----
    {
        GemmArgs ar{};
        const unsigned* Aarr[6] = { img_tf, txt_tf, txt_tf, txt_tf, img_tf, img_tf };
        const unsigned* Warr[6] = { (const unsigned*)ia[0], (const unsigned*)ia[2],
                                    (const unsigned*)ia[4], (const unsigned*)ta[0],
                                    (const unsigned*)ta[2], (const unsigned*)ta[4] };
        const float*    Barr[6] = { ia[1], ia[3], ia[5], ta[1], ta[3], ta[5] };
        float*          Carr[6] = { Qb, Kb, Vb, Qb + NEL, Kb + NEL, Vb + NEL };
        for (int s = 0; s < 6; s++) {
            ar.A[s] = Aarr[s]; ar.W[s] = Warr[s]; ar.bias[s] = Barr[s];
            ar.resid[s] = nullptr; ar.C[s] = Carr[s]; ar.Ctf[s] = nullptr; ar.K[s] = 1024;
        }
        gemm_tf32_kernel<<<dim3(GX, GY, 6), blk, GEMM_SMEM>>>(ar);
    }

    // ---- launch 3: CTA-tiled sliding-window attention ----
    swattn_tiled<<<dim3(8, 8, 2), 512, ATT_SMEM>>>(ia[3], ia[5], ta[3], ta[5]);

    // ---- launch 4: output projections + residual (z=2) ----
    {
        GemmArgs ar{};
        ar.A[0] = Otf;       ar.W[0] = (const unsigned*)ia[6]; ar.bias[0] = ia[7];
        ar.resid[0] = img;   ar.C[0] = out;       ar.Ctf[0] = nullptr; ar.K[0] = 1024;
        ar.A[1] = Otf + NEL; ar.W[1] = (const unsigned*)ta[6]; ar.bias[1] = ta[7];
        ar.resid[1] = txt;   ar.C[1] = out + NEL; ar.Ctf[1] = nullptr; ar.K[1] = 1024;
        gemm_tf32_kernel<<<dim3(GX, GY, 2), blk, GEMM_SMEM>>>(ar);
    }
}